// round 14
// baseline (speedup 1.0000x reference)
#include <cuda_runtime.h>
#include <cfloat>

#define SPATIAL_SCALE 0.0625f
#define CC 256
#define HH 64
#define WW 64
#define HW 4096
#define KK 128
#define PH 7
#define PW 7
#define NBIN 49

// 8MB NHWC scratch: xt[b][h][w][c], float4-aligned
__device__ __align__(16) float g_xt[2 * HW * CC];

// ---------------- Kernel A: NCHW -> NHWC transpose ----------------
// Tile: 32c x 64hw. Grid (64, 8, 2) = 1024 blocks, 256 threads. (best measured ~2.7us)
__global__ __launch_bounds__(256) void transpose_kernel(const float* __restrict__ x) {
    __shared__ float tile[32][65];
    const int b   = blockIdx.z;
    const int hw0 = blockIdx.x * 64;
    const int c0  = blockIdx.y * 32;
    const int t   = threadIdx.x;

    const int q  = t & 15;
    const int cL = t >> 4;
#pragma unroll
    for (int j = 0; j < 2; ++j) {
        const int c = cL + j * 16;
        const float4 v = *reinterpret_cast<const float4*>(
            x + ((long)(b * CC + c0 + c)) * HW + hw0 + q * 4);
        tile[c][q * 4 + 0] = v.x;
        tile[c][q * 4 + 1] = v.y;
        tile[c][q * 4 + 2] = v.z;
        tile[c][q * 4 + 3] = v.w;
    }
    __syncthreads();

    const int cq = t & 7;
    const int h0 = t >> 3;
#pragma unroll
    for (int j = 0; j < 2; ++j) {
        const int hh = h0 + j * 32;
        float4 v;
        v.x = tile[cq * 4 + 0][hh];
        v.y = tile[cq * 4 + 1][hh];
        v.z = tile[cq * 4 + 2][hh];
        v.w = tile[cq * 4 + 3][hh];
        *reinterpret_cast<float4*>(
            g_xt + ((long)(b * HW + hw0 + hh)) * CC + c0 + cq * 4) = v;
    }
}

__device__ __forceinline__ float4 f4max(float4 a, float4 b) {
    a.x = fmaxf(a.x, b.x);
    a.y = fmaxf(a.y, b.y);
    a.z = fmaxf(a.z, b.z);
    a.w = fmaxf(a.w, b.w);
    return a;
}

// Strides in float4 units: w+1 -> +64, h+1 -> +4096, second c-quad -> +32
#define SW4 64
#define SH4 4096
#define SC4 32

// ---------------- Kernel B: pool. Block = (k, ph). 224 threads, ALL 256 channels. ----------------
// Warp = one (ph,pw) bin x 256 channels; each thread 2 quads -> 8 LDG.128 in flight.
__global__ __launch_bounds__(224, 4) void roipool_kernel(
        const float* __restrict__ rois,
        float* __restrict__ out) {
    __shared__ float4 res4[PH][65];     // [pw][c-quad 0..63], conflict-free

    const int bx = blockIdx.x;
    const int k  = bx / 7;
    const int ph = bx - k * 7;

    const int t  = threadIdx.x;         // 0..223
    const int pw = t >> 5;              // warp-uniform
    const int cq = t & 31;              // first channel quad (second is cq+32)

    // ---- ROI geometry (bit-exact, verbatim) ----
    const float* r = rois + k * 5;
    const int b  = (int)__ldg(&r[0]);
    const int x1 = (int)rintf(__ldg(&r[1]) * SPATIAL_SCALE);
    const int y1 = (int)rintf(__ldg(&r[2]) * SPATIAL_SCALE);
    const int x2 = (int)rintf(__ldg(&r[3]) * SPATIAL_SCALE);
    const int y2 = (int)rintf(__ldg(&r[4]) * SPATIAL_SCALE);

    const int roi_w = max(x2 - x1 + 1, 1);
    const int roi_h = max(y2 - y1 + 1, 1);

    const float INV7 = __uint_as_float(0x3E124925u);  // fl(1/7): XLA recip-mul
    const float bw = __fmul_rn((float)roi_w, INV7);
    const float bh = __fmul_rn((float)roi_h, INV7);

    int hs = (int)floorf(__fmul_rn((float)ph, bh)) + y1;
    int he = (int)ceilf(__fmul_rn((float)(ph + 1), bh)) + y1;
    int ws = (int)floorf(__fmul_rn((float)pw, bw)) + x1;
    int we = (int)ceilf(__fmul_rn((float)(pw + 1), bw)) + x1;
    hs = min(max(hs, 0), HH);
    he = min(max(he, 0), HH);
    ws = min(max(ws, 0), WW);
    we = min(max(we, 0), WW);

    float4 mA, mB;   // results for quad cq and quad cq+32
    if (hs >= he || ws >= we) {
        mA = make_float4(0.f, 0.f, 0.f, 0.f);
        mB = mA;
    } else {
        const float4 NEG = make_float4(-FLT_MAX, -FLT_MAX, -FLT_MAX, -FLT_MAX);
        float4 a0 = NEG, a1 = NEG, a2 = NEG, a3 = NEG;   // quad A: (row0/1) x (w0/1)
        float4 b0 = NEG, b1 = NEG, b2 = NEG, b3 = NEG;   // quad B
        const int n = we - ws;
        const float4* p = reinterpret_cast<const float4*>(g_xt)
                        + (b * HW * (CC / 4)) + ((hs << 6) + ws) * SW4 + cq;
        int rows = he - hs;
        for (; rows >= 2; rows -= 2) {
            const float4* q = p;
            int w = n;
            for (; w >= 2; w -= 2) {
                a0 = f4max(a0, q[0]);
                b0 = f4max(b0, q[SC4]);
                a1 = f4max(a1, q[SW4]);
                b1 = f4max(b1, q[SW4 + SC4]);
                a2 = f4max(a2, q[SH4]);
                b2 = f4max(b2, q[SH4 + SC4]);
                a3 = f4max(a3, q[SH4 + SW4]);
                b3 = f4max(b3, q[SH4 + SW4 + SC4]);
                q += 2 * SW4;
            }
            if (w) {
                a0 = f4max(a0, q[0]);
                b0 = f4max(b0, q[SC4]);
                a2 = f4max(a2, q[SH4]);
                b2 = f4max(b2, q[SH4 + SC4]);
            }
            p += 2 * SH4;
        }
        if (rows) {   // trailing row
            const float4* q = p;
            int w = n;
            for (; w >= 2; w -= 2) {
                a0 = f4max(a0, q[0]);
                b0 = f4max(b0, q[SC4]);
                a1 = f4max(a1, q[SW4]);
                b1 = f4max(b1, q[SW4 + SC4]);
                q += 2 * SW4;
            }
            if (w) {
                a0 = f4max(a0, q[0]);
                b0 = f4max(b0, q[SC4]);
            }
        }
        mA = f4max(f4max(a0, a1), f4max(a2, a3));   // max reordering is exact
        mB = f4max(f4max(b0, b1), f4max(b2, b3));
    }
    res4[pw][cq]      = mA;
    res4[pw][cq + 32] = mB;
    __syncthreads();

    // Store: block owns out[(k*256+c)*49 + ph*7 + p], c in [0,256), p in [0,7)
    const float* resf = reinterpret_cast<const float*>(res4);   // idx = pw*260 + c
    float* ob = out + ((long)k * CC) * NBIN + ph * PW;
#pragma unroll
    for (int i = 0; i < 8; ++i) {
        const int j = t + i * 224;      // 0..1791
        const int c = j / 7;
        const int p = j - c * 7;
        ob[(long)c * NBIN + p] = resf[p * 260 + c];
    }
}

extern "C" void kernel_launch(void* const* d_in, const int* in_sizes, int n_in,
                              void* d_out, int out_size) {
    const float* x    = (const float*)d_in[0];
    const float* rois = (const float*)d_in[1];
    if (n_in >= 2 && in_sizes[0] == KK * 5) {
        x    = (const float*)d_in[1];
        rois = (const float*)d_in[0];
    }
    float* out = (float*)d_out;

    dim3 gA(HW / 64, CC / 32, 2);    // 1024 blocks
    transpose_kernel<<<gA, 256>>>(x);

    roipool_kernel<<<KK * PH, 224>>>(rois, out);  // 896 blocks
}

// round 15
// speedup vs baseline: 1.2521x; 1.2521x over previous
#include <cuda_runtime.h>
#include <cfloat>

#define SPATIAL_SCALE 0.0625f
#define CC 256
#define HH 64
#define WW 64
#define HW 4096
#define KK 128
#define PH 7
#define PW 7
#define NBIN 49

// 8MB NHWC scratch: xt[b][h][w][c], float4-aligned
__device__ __align__(16) float g_xt[2 * HW * CC];

// Precomputed per-ROI geometry (packed lo|hi<<16)
__device__ int g_b[KK];
__device__ int g_hr[KK * PH];
__device__ int g_wr[KK * PW];

// ---------------- Kernel A: NCHW -> NHWC transpose + ROI geometry ----------------
// Tile: 32c x 64hw. Grid (64, 8, 2) = 1024 blocks, 256 threads.
__global__ __launch_bounds__(256) void transpose_kernel(const float* __restrict__ x,
                                                        const float* __restrict__ rois) {
    // Block (0,0,0): also precompute ROI geometry (independent of transpose data).
    if (blockIdx.x == 0 && blockIdx.y == 0 && blockIdx.z == 0 && threadIdx.x < KK) {
        const int k = threadIdx.x;
        const float* r = rois + k * 5;
        // ---- bit-exact razor math (verbatim) ----
        const int b  = (int)__ldg(&r[0]);
        const int x1 = (int)rintf(__ldg(&r[1]) * SPATIAL_SCALE);
        const int y1 = (int)rintf(__ldg(&r[2]) * SPATIAL_SCALE);
        const int x2 = (int)rintf(__ldg(&r[3]) * SPATIAL_SCALE);
        const int y2 = (int)rintf(__ldg(&r[4]) * SPATIAL_SCALE);

        const int roi_w = max(x2 - x1 + 1, 1);
        const int roi_h = max(y2 - y1 + 1, 1);

        const float INV7 = __uint_as_float(0x3E124925u);  // fl(1/7): XLA recip-mul
        const float bw = __fmul_rn((float)roi_w, INV7);
        const float bh = __fmul_rn((float)roi_h, INV7);

        g_b[k] = b;
#pragma unroll
        for (int j = 0; j < 7; ++j) {
            int hs = (int)floorf(__fmul_rn((float)j, bh)) + y1;
            int he = (int)ceilf(__fmul_rn((float)(j + 1), bh)) + y1;
            int ws = (int)floorf(__fmul_rn((float)j, bw)) + x1;
            int we = (int)ceilf(__fmul_rn((float)(j + 1), bw)) + x1;
            hs = min(max(hs, 0), HH);
            he = min(max(he, 0), HH);
            ws = min(max(ws, 0), WW);
            we = min(max(we, 0), WW);
            g_hr[k * PH + j] = hs | (he << 16);
            g_wr[k * PW + j] = ws | (we << 16);
        }
    }

    __shared__ float tile[32][65];
    const int b   = blockIdx.z;
    const int hw0 = blockIdx.x * 64;
    const int c0  = blockIdx.y * 32;
    const int t   = threadIdx.x;

    const int q  = t & 15;
    const int cL = t >> 4;
#pragma unroll
    for (int j = 0; j < 2; ++j) {
        const int c = cL + j * 16;
        const float4 v = *reinterpret_cast<const float4*>(
            x + ((long)(b * CC + c0 + c)) * HW + hw0 + q * 4);
        tile[c][q * 4 + 0] = v.x;
        tile[c][q * 4 + 1] = v.y;
        tile[c][q * 4 + 2] = v.z;
        tile[c][q * 4 + 3] = v.w;
    }
    __syncthreads();

    const int cq = t & 7;
    const int h0 = t >> 3;
#pragma unroll
    for (int j = 0; j < 2; ++j) {
        const int hh = h0 + j * 32;
        float4 v;
        v.x = tile[cq * 4 + 0][hh];
        v.y = tile[cq * 4 + 1][hh];
        v.z = tile[cq * 4 + 2][hh];
        v.w = tile[cq * 4 + 3][hh];
        *reinterpret_cast<float4*>(
            g_xt + ((long)(b * HW + hw0 + hh)) * CC + c0 + cq * 4) = v;
    }
}

__device__ __forceinline__ float4 f4max(float4 a, float4 b) {
    a.x = fmaxf(a.x, b.x);
    a.y = fmaxf(a.y, b.y);
    a.z = fmaxf(a.z, b.z);
    a.w = fmaxf(a.w, b.w);
    return a;
}

// Strides in float4 units: w+1 -> +64, h+1 -> +4096
#define SW4 64
#define SH4 4096

// ---------------- Kernel B: pool. Block = (k, c-chunk128, ph). 224 threads. ----------------
// Geometry via precomputed broadcast loads; LDG.128 immediate offsets; occ-capped regs.
__global__ __launch_bounds__(224, 6) void roipool_kernel(float* __restrict__ out) {
    __shared__ float4 res4[PH][33];     // [pw][c-quad], conflict-free

    const int bx  = blockIdx.x;
    const int k   = bx / 14;
    const int rem = bx - k * 14;
    const int c0  = (rem / 7) << 7;     // 0 or 128
    const int ph  = rem % 7;

    const int t  = threadIdx.x;         // 0..223
    const int pw = t >> 5;              // warp-uniform
    const int cq = t & 31;              // channel quad

    const int b  = __ldg(&g_b[k]);
    const int hr = __ldg(&g_hr[k * PH + ph]);
    const int wr = __ldg(&g_wr[k * PW + pw]);
    const int hs = hr & 0xFFFF, he = hr >> 16;
    const int ws = wr & 0xFFFF, we = wr >> 16;

    float4 m;
    if (hs >= he || ws >= we) {
        m = make_float4(0.f, 0.f, 0.f, 0.f);
    } else {
        float4 m0 = make_float4(-FLT_MAX, -FLT_MAX, -FLT_MAX, -FLT_MAX);
        float4 m1 = m0, m2 = m0, m3 = m0;
        const int n = we - ws;
        const float4* p = reinterpret_cast<const float4*>(g_xt)
                        + (b * HW * (CC / 4)) + ((hs << 6) + ws) * SW4 + (c0 >> 2) + cq;
        int rows = he - hs;
        for (; rows >= 2; rows -= 2) {
            const float4* q = p;
            int w = n;
            for (; w >= 2; w -= 2) {
                m0 = f4max(m0, q[0]);
                m1 = f4max(m1, q[SW4]);
                m2 = f4max(m2, q[SH4]);
                m3 = f4max(m3, q[SH4 + SW4]);
                q += 2 * SW4;
            }
            if (w) {
                m0 = f4max(m0, q[0]);
                m2 = f4max(m2, q[SH4]);
            }
            p += 2 * SH4;
        }
        if (rows) {
            const float4* q = p;
            int w = n;
            for (; w >= 2; w -= 2) {
                m0 = f4max(m0, q[0]);
                m1 = f4max(m1, q[SW4]);
                q += 2 * SW4;
            }
            if (w) m0 = f4max(m0, q[0]);
        }
        m = f4max(f4max(m0, m1), f4max(m2, m3));   // max reordering is exact
    }
    res4[pw][cq] = m;
    __syncthreads();

    // Store: block owns out[(k*256+c0+c)*49 + ph*7 + p], c in [0,128), p in [0,7)
    const float* resf = reinterpret_cast<const float*>(res4);   // idx = pw*132 + c
    float* ob = out + ((long)(k * CC + c0)) * NBIN + ph * PW;
#pragma unroll
    for (int i = 0; i < 4; ++i) {
        const int j = t + i * 224;      // 0..895
        const int c = j / 7;
        const int p = j - c * 7;
        ob[(long)c * NBIN + p] = resf[p * 132 + c];
    }
}

extern "C" void kernel_launch(void* const* d_in, const int* in_sizes, int n_in,
                              void* d_out, int out_size) {
    const float* x    = (const float*)d_in[0];
    const float* rois = (const float*)d_in[1];
    if (n_in >= 2 && in_sizes[0] == KK * 5) {
        x    = (const float*)d_in[1];
        rois = (const float*)d_in[0];
    }
    float* out = (float*)d_out;

    dim3 gA(HW / 64, CC / 32, 2);    // 1024 blocks
    transpose_kernel<<<gA, 256>>>(x, rois);

    roipool_kernel<<<KK * 2 * PH, 224>>>(out);  // 1792 blocks
}